// round 17
// baseline (speedup 1.0000x reference)
#include <cuda_runtime.h>
#include <cuda_bf16.h>
#include <math.h>

// Problem constants (fixed shapes per reference)
#define NU_  40000
#define NI_  60000
#define NN_  100000
#define DF_  1024
#define DL_  128
#define DI_  64
#define NE_  1600000

// Scratch buffers (device globals: allocation-guard safe)
__device__ __align__(16) __nv_bfloat16 g_x [(size_t)NN_ * DL_];  // x (bf16)
__device__ __align__(16) __nv_bfloat16 g_xw[(size_t)NN_ * DL_];  // conv out (bf16)
__device__ __align__(16) __nv_bfloat16 g_h [(size_t)NN_ * DL_];  // leaky(segsum) bf16
__device__ __align__(16) __nv_bfloat16 g_x2[(size_t)NN_ * DI_];  // layer-1 out (bf16)
__device__ float g_xhat[(size_t)NN_ * DI_];                      // lin output fp32
// bf16 weight copies (built on side stream)
__device__ __align__(16) __nv_bfloat16 g_wmlp [DL_ * DF_];  // mlp_w   [n=128][k=1024]
__device__ __align__(16) __nv_bfloat16 g_wc1  [DL_ * DL_];  // conv1_w^T [n=128][k=128]
__device__ __align__(16) __nv_bfloat16 g_wc2  [DI_ * DI_];  // conv2_w^T [n=64][k=64]
__device__ __align__(16) __nv_bfloat16 g_wlin1[DI_ * DL_];  // lin1_w  [n=64][k=128]
__device__ __align__(16) __nv_bfloat16 g_wg1  [DI_ * DL_];  // g1_w    [n=64][k=128]
__device__ __align__(16) __nv_bfloat16 g_wlin2[DI_ * DI_];  // lin2_w  [n=64][k=64]
__device__ __align__(16) __nv_bfloat16 g_wg2  [DI_ * DI_];  // g2_w    [n=64][k=64]
// CSR build scratch
__device__ int g_cnt [NN_ + 1];
__device__ int g_offs[NN_ + 1];
__device__ int g_part[128];
__device__ int g_pos [NN_];
__device__ int g_srcs[NE_];

#define MODE_NORM  0   // v = acc + bias; row L2 norm
#define MODE_PLAIN 1   // v = acc
#define MODE_LIN   2   // v = leaky(acc + bias) + aux[row,col]
#define MODE_G     3   // v = leaky(acc + bias + aux[row,col]); A = pre-leaky'd bf16

__device__ __forceinline__ float leaky_(float v) { return v > 0.0f ? v : 0.01f * v; }

__device__ __forceinline__ unsigned f2bf2(float lo, float hi) {
    __nv_bfloat162 h = __floats2bfloat162_rn(lo, hi);
    return *reinterpret_cast<unsigned*>(&h);
}

// bf16 m16n8k16 mma, fp32 accumulate
__device__ __forceinline__ void mma_bf16(float* d, const unsigned* a, const unsigned* b) {
    asm volatile(
        "mma.sync.aligned.m16n8k16.row.col.f32.bf16.bf16.f32 "
        "{%0,%1,%2,%3}, {%4,%5,%6,%7}, {%8,%9}, {%0,%1,%2,%3};"
        : "+f"(d[0]), "+f"(d[1]), "+f"(d[2]), "+f"(d[3])
        : "r"(a[0]), "r"(a[1]), "r"(a[2]), "r"(a[3]), "r"(b[0]), "r"(b[1]));
}

__device__ __forceinline__ void ldsm_x4(unsigned* r, unsigned addr) {
    asm volatile("ldmatrix.sync.aligned.m8n8.x4.shared.b16 {%0,%1,%2,%3}, [%4];"
                 : "=r"(r[0]), "=r"(r[1]), "=r"(r[2]), "=r"(r[3]) : "r"(addr));
}

// ---------------------------------------------------------------------------
// Unified bf16 tensor-core GEMM: C[M,BN] = A[M,K] @ B[BN,K]^T
// BK=32 (2 k16 MMA steps per tile), double-buffered, 256 threads.
// B is always bf16 [n][k] (pre-converted). A bf16 unless ABF16=false.
// Fragment loads via ldmatrix.x4 on SW=20-word rows (conflict-free).
// ---------------------------------------------------------------------------
template <int BN, int MODE, bool ABF16, bool OUTBF16>
__global__ __launch_bounds__(256) void mma_gemm(
    const void* __restrict__ Av, const __nv_bfloat16* __restrict__ B,
    void* __restrict__ Cv, int M, int K,
    const float* __restrict__ bias, const float* __restrict__ aux)
{
    constexpr int BM = 128, BK = 32, SW = 20;
    constexpr int WARPS_M = (BN == 128) ? 2 : 4;
    constexpr int WM = BM / WARPS_M;
    constexpr int MT = WM / 16;
    constexpr int NT = 4;

    __shared__ unsigned sA[2][BM * SW];
    __shared__ unsigned sB[2][BN * SW];
    __shared__ float sNorm[(MODE == MODE_NORM) ? BM : 1];

    const int t    = threadIdx.x;
    const int wid  = t >> 5;
    const int lane = t & 31;
    const int gid  = lane >> 2;
    const int tidg = lane & 3;
    const int wm   = (wid % WARPS_M) * WM;
    const int wn   = (wid / WARPS_M) * 32;
    const int m0   = blockIdx.x * BM;

    const unsigned sA_u = (unsigned)__cvta_generic_to_shared(&sA[0][0]);
    const unsigned sB_u = (unsigned)__cvta_generic_to_shared(&sB[0][0]);

    const int a_row = (lane & 7) + ((lane >> 3) & 1) * 8;
    const int a_kw  = (lane >> 4) * 4;
    const int aw_off = a_row * SW + a_kw;
    const int b_row = (lane & 7) + (lane >> 4) * 8;
    const int b_kw  = ((lane >> 3) & 1) * 4;
    const int bw_off = b_row * SW + b_kw;

    uint4  aRegV[2];
    float4 aRegF[4];
    uint4  bRegV[2];

    float acc[MT][NT][4];
#pragma unroll
    for (int i = 0; i < MT; i++)
#pragma unroll
        for (int j = 0; j < NT; j++)
#pragma unroll
            for (int q = 0; q < 4; q++) acc[i][j][q] = 0.0f;

#define LOAD_A(K0)                                                            \
    if (ABF16) {                                                              \
        const __nv_bfloat16* Ab = (const __nv_bfloat16*)Av;                   \
        _Pragma("unroll")                                                     \
        for (int i = 0; i < 2; i++) {                                         \
            int fid = t + i * 256;                                            \
            int r = fid >> 2, c = fid & 3;                                    \
            int row = m0 + r;                                                 \
            aRegV[i] = make_uint4(0u, 0u, 0u, 0u);                            \
            if (row < M)                                                      \
                aRegV[i] = *(const uint4*)&Ab[(size_t)row * K + (K0) + c * 8];\
        }                                                                     \
    } else {                                                                  \
        const float* Af = (const float*)Av;                                   \
        _Pragma("unroll")                                                     \
        for (int i = 0; i < 4; i++) {                                         \
            int fid = t + i * 256;                                            \
            int r = fid >> 3, c = fid & 7;                                    \
            int row = m0 + r;                                                 \
            float4 v = make_float4(0.f, 0.f, 0.f, 0.f);                       \
            if (row < M) v = *(const float4*)&Af[(size_t)row*K + (K0) + c*4]; \
            aRegF[i] = v;                                                     \
        }                                                                     \
    }

#define STORE_A(BUF)                                                          \
    if (ABF16) {                                                              \
        _Pragma("unroll")                                                     \
        for (int i = 0; i < 2; i++) {                                         \
            int fid = t + i * 256;                                            \
            int r = fid >> 2, c = fid & 3;                                    \
            *(uint4*)&sA[BUF][r * SW + c * 4] = aRegV[i];                     \
        }                                                                     \
    } else {                                                                  \
        _Pragma("unroll")                                                     \
        for (int i = 0; i < 4; i++) {                                         \
            int fid = t + i * 256;                                            \
            int r = fid >> 3, c = fid & 7;                                    \
            float4 v = aRegF[i];                                              \
            uint2 u = make_uint2(f2bf2(v.x, v.y), f2bf2(v.z, v.w));           \
            *(uint2*)&sA[BUF][r * SW + c * 2] = u;                            \
        }                                                                     \
    }

#define LOAD_B(K0)                                                            \
    if (BN == 128) {                                                          \
        _Pragma("unroll")                                                     \
        for (int i = 0; i < 2; i++) {                                         \
            int fid = t + i * 256;                                            \
            int n = fid >> 2, c = fid & 3;                                    \
            bRegV[i] = *(const uint4*)&B[(size_t)n * K + (K0) + c * 8];       \
        }                                                                     \
    } else {                                                                  \
        int n = t >> 2, c = t & 3;                                            \
        bRegV[0] = *(const uint4*)&B[(size_t)n * K + (K0) + c * 8];           \
    }

#define STORE_B(BUF)                                                          \
    if (BN == 128) {                                                          \
        _Pragma("unroll")                                                     \
        for (int i = 0; i < 2; i++) {                                         \
            int fid = t + i * 256;                                            \
            int n = fid >> 2, c = fid & 3;                                    \
            *(uint4*)&sB[BUF][n * SW + c * 4] = bRegV[i];                     \
        }                                                                     \
    } else {                                                                  \
        int n = t >> 2, c = t & 3;                                            \
        *(uint4*)&sB[BUF][n * SW + c * 4] = bRegV[0];                         \
    }

    const int nk = K / BK;
    LOAD_A(0); LOAD_B(0);
    STORE_A(0); STORE_B(0);
    __syncthreads();

    for (int it = 0; it < nk; it++) {
        const int buf = it & 1;
        if (it + 1 < nk) { LOAD_A((it + 1) * BK); LOAD_B((it + 1) * BK); }

        const unsigned aBufU = sA_u + (unsigned)(buf * BM * SW) * 4u;
        const unsigned bBufU = sB_u + (unsigned)(buf * BN * SW) * 4u;

#pragma unroll
        for (int s = 0; s < 2; s++) {
            unsigned af[MT][4];
#pragma unroll
            for (int mt = 0; mt < MT; mt++)
                ldsm_x4(af[mt], aBufU +
                        (unsigned)((wm + mt * 16) * SW + s * 8 + aw_off) * 4u);
            unsigned bf[2][4];
#pragma unroll
            for (int p = 0; p < 2; p++)
                ldsm_x4(bf[p], bBufU +
                        (unsigned)((wn + p * 16) * SW + s * 8 + bw_off) * 4u);
#pragma unroll
            for (int mt = 0; mt < MT; mt++)
#pragma unroll
                for (int nt = 0; nt < NT; nt++)
                    mma_bf16(acc[mt][nt], af[mt], &bf[nt >> 1][(nt & 1) * 2]);
        }

        if (it + 1 < nk) {
            STORE_A(buf ^ 1); STORE_B(buf ^ 1);
            __syncthreads();
        }
    }

    // ---- epilogue ----
    if (MODE == MODE_NORM) {
        if (t < BM) sNorm[t] = 0.0f;
        __syncthreads();
#pragma unroll
        for (int mt = 0; mt < MT; mt++)
#pragma unroll
            for (int nt = 0; nt < NT; nt++) {
                int col = wn + nt * 8 + 2 * tidg;
#pragma unroll
                for (int half = 0; half < 2; half++) {
                    int rl = wm + mt * 16 + gid + half * 8;
                    if (m0 + rl >= M) continue;
                    float v0 = acc[mt][nt][half * 2 + 0] + bias[col];
                    float v1 = acc[mt][nt][half * 2 + 1] + bias[col + 1];
                    acc[mt][nt][half * 2 + 0] = v0;
                    acc[mt][nt][half * 2 + 1] = v1;
                    atomicAdd(&sNorm[rl], v0 * v0 + v1 * v1);
                }
            }
        __syncthreads();
        if (t < BM) sNorm[t] = 1.0f / fmaxf(sqrtf(sNorm[t]), 1e-12f);
        __syncthreads();
    }

#pragma unroll
    for (int mt = 0; mt < MT; mt++)
#pragma unroll
        for (int nt = 0; nt < NT; nt++) {
            int col = wn + nt * 8 + 2 * tidg;
#pragma unroll
            for (int half = 0; half < 2; half++) {
                int rl = wm + mt * 16 + gid + half * 8;
                int row = m0 + rl;
                if (row >= M) continue;
                float v0 = acc[mt][nt][half * 2 + 0];
                float v1 = acc[mt][nt][half * 2 + 1];
                if (MODE == MODE_NORM) {
                    float inv = sNorm[rl];
                    v0 *= inv; v1 *= inv;
                } else if (MODE == MODE_LIN) {
                    v0 = leaky_(v0 + bias[col]) + aux[(size_t)row * BN + col];
                    v1 = leaky_(v1 + bias[col + 1]) + aux[(size_t)row * BN + col + 1];
                } else if (MODE == MODE_G) {
                    v0 = leaky_(v0 + bias[col] + aux[(size_t)row * BN + col]);
                    v1 = leaky_(v1 + bias[col + 1] + aux[(size_t)row * BN + col + 1]);
                }
                if (OUTBF16) {
                    __nv_bfloat16* C = (__nv_bfloat16*)Cv;
                    *(__nv_bfloat162*)&C[(size_t)row * BN + col] =
                        __floats2bfloat162_rn(v0, v1);
                } else {
                    float* C = (float*)Cv;
                    *(float2*)&C[(size_t)row * BN + col] = make_float2(v0, v1);
                }
            }
        }
#undef LOAD_A
#undef STORE_A
#undef LOAD_B
#undef STORE_B
}

// ---------------------------------------------------------------------------
// Weight transpose + bf16 convert: src [Kdim][Ndim] fp32 -> dst [Ndim][Kdim] bf16
// ---------------------------------------------------------------------------
__global__ void transpose_cvt(const float* __restrict__ src,
                              __nv_bfloat16* __restrict__ dst, int Kdim, int Ndim)
{
    int i = blockIdx.x * 256 + threadIdx.x;
    if (i < Kdim * Ndim) {
        int k = i / Ndim, n = i % Ndim;
        dst[(size_t)n * Kdim + k] = __float2bfloat16(src[i]);
    }
}

// Plain elementwise fp32 -> bf16 (4 per thread)
__global__ void cvt_bf16(const float* __restrict__ src,
                         __nv_bfloat16* __restrict__ dst, int n)
{
    int i = (blockIdx.x * 256 + threadIdx.x) * 4;
    if (i < n) {
        float4 v = *(const float4*)&src[i];
        uint2 u = make_uint2(f2bf2(v.x, v.y), f2bf2(v.z, v.w));
        *(uint2*)&dst[i] = u;
    }
}

// ---------------------------------------------------------------------------
// Fused copy + row-wise L2 normalize for preference rows; bf16 output
// ---------------------------------------------------------------------------
__global__ void pref_norm_kernel(const float* __restrict__ src,
                                 __nv_bfloat16* __restrict__ dst, int nrows)
{
    int warp = (blockIdx.x * blockDim.x + threadIdx.x) >> 5;
    int lane = threadIdx.x & 31;
    if (warp >= nrows) return;
    float4 v = *(const float4*)&src[(size_t)warp * 128 + lane * 4];
    float ss = v.x * v.x + v.y * v.y + v.z * v.z + v.w * v.w;
#pragma unroll
    for (int o = 16; o; o >>= 1) ss += __shfl_xor_sync(0xffffffffu, ss, o);
    float inv = 1.0f / fmaxf(sqrtf(ss), 1e-12f);
    uint2 u = make_uint2(f2bf2(v.x * inv, v.y * inv), f2bf2(v.z * inv, v.w * inv));
    *(uint2*)&dst[(size_t)warp * 128 + lane * 4] = u;
}

// ---------------------------------------------------------------------------
// CSR build: histogram of dst, 3-phase exclusive scan, src reorder by dst
// ---------------------------------------------------------------------------
__global__ void hist_kernel(const int* __restrict__ ei, int* __restrict__ cnt)
{
    int e = blockIdx.x * blockDim.x + threadIdx.x;
    if (e < NE_) atomicAdd(&cnt[__ldg(&ei[NE_ + e])], 1);
}

__global__ void scan1_kernel(const int* __restrict__ in, int* __restrict__ out,
                             int* __restrict__ part, int n)
{
    __shared__ int s[1024];
    int i = blockIdx.x * 1024 + threadIdx.x;
    int v = (i < n) ? in[i] : 0;
    s[threadIdx.x] = v;
    __syncthreads();
#pragma unroll
    for (int o = 1; o < 1024; o <<= 1) {
        int y = (threadIdx.x >= o) ? s[threadIdx.x - o] : 0;
        __syncthreads();
        s[threadIdx.x] += y;
        __syncthreads();
    }
    if (i < n) out[i] = s[threadIdx.x] - v;
    if (threadIdx.x == 1023) part[blockIdx.x] = s[1023];
}

__global__ void scan2_kernel(int* __restrict__ part, int nb)
{
    __shared__ int s[128];
    int v = (threadIdx.x < nb) ? part[threadIdx.x] : 0;
    s[threadIdx.x] = v;
    __syncthreads();
#pragma unroll
    for (int o = 1; o < 128; o <<= 1) {
        int y = (threadIdx.x >= o) ? s[threadIdx.x - o] : 0;
        __syncthreads();
        s[threadIdx.x] += y;
        __syncthreads();
    }
    if (threadIdx.x < nb) part[threadIdx.x] = s[threadIdx.x] - v;  // exclusive
}

__global__ void scan3_kernel(int* __restrict__ out, const int* __restrict__ part, int n)
{
    int i = blockIdx.x * 1024 + threadIdx.x;
    if (i < n) out[i] += part[blockIdx.x];
}

__global__ void reorder_kernel(const int* __restrict__ ei, int* __restrict__ pos,
                               int* __restrict__ srcs)
{
    int e = blockIdx.x * blockDim.x + threadIdx.x;
    if (e >= NE_) return;
    int d = __ldg(&ei[NE_ + e]);
    int idx = atomicAdd(&pos[d], 1);
    srcs[idx] = __ldg(&ei[e]);
}

// ---------------------------------------------------------------------------
// Atomic-free segmented scatter, ONE FULL WARP PER NODE (zero divergence):
//   D=128: lane covers 4 bf16 (8B);  D=64: lane covers 2 bf16 (4B).
// fp32 accumulate; output = leaky(sum) as bf16. Per-element accumulation
// order identical to previous version (same edge sequence, a/b banks).
// ---------------------------------------------------------------------------
template <int D>
__global__ void seg_scatter(const __nv_bfloat16* __restrict__ xw,
                            const int* __restrict__ offs,
                            const int* __restrict__ srcs,
                            __nv_bfloat16* __restrict__ h)
{
    constexpr int EPL = D / 32;    // bf16 elements per lane (4 or 2)
    int node = (blockIdx.x * blockDim.x + threadIdx.x) >> 5;
    int lane = threadIdx.x & 31;
    if (node >= NN_) return;

    int s   = __ldg(&offs[node]);
    int end = __ldg(&offs[node + 1]);

    float a[EPL], b[EPL];
#pragma unroll
    for (int j = 0; j < EPL; j++) { a[j] = 0.f; b[j] = 0.f; }

#define ACCL(dst, u0, u1)                                                   \
    {                                                                       \
        float2 f0 = __bfloat1622float2(*(const __nv_bfloat162*)&(u0));      \
        dst[0] += f0.x; dst[1] += f0.y;                                     \
        if (EPL == 4) {                                                     \
            float2 f1 = __bfloat1622float2(*(const __nv_bfloat162*)&(u1));  \
            dst[2] += f1.x; dst[3] += f1.y;                                 \
        }                                                                   \
    }

    int i = s;
    if (EPL == 4) {
        const uint2* xw2 = (const uint2*)xw;
        for (; i + 3 < end; i += 4) {
            int s0 = __ldg(&srcs[i + 0]);
            int s1 = __ldg(&srcs[i + 1]);
            int s2 = __ldg(&srcs[i + 2]);
            int s3 = __ldg(&srcs[i + 3]);
            uint2 u0 = xw2[(size_t)s0 * 32 + lane];
            uint2 u1 = xw2[(size_t)s1 * 32 + lane];
            uint2 u2 = xw2[(size_t)s2 * 32 + lane];
            uint2 u3 = xw2[(size_t)s3 * 32 + lane];
            ACCL(a, u0.x, u0.y); ACCL(b, u1.x, u1.y);
            ACCL(a, u2.x, u2.y); ACCL(b, u3.x, u3.y);
        }
        for (; i < end; i++) {
            int s0 = __ldg(&srcs[i]);
            uint2 u0 = xw2[(size_t)s0 * 32 + lane];
            ACCL(a, u0.x, u0.y);
        }
        uint2 r;
        r.x = f2bf2(leaky_(a[0] + b[0]), leaky_(a[1] + b[1]));
        r.y = f2bf2(leaky_(a[2] + b[2]), leaky_(a[3] + b[3]));
        *(uint2*)&h[(size_t)node * D + lane * 4] = r;
    } else {
        const unsigned* xw1 = (const unsigned*)xw;
        for (; i + 3 < end; i += 4) {
            int s0 = __ldg(&srcs[i + 0]);
            int s1 = __ldg(&srcs[i + 1]);
            int s2 = __ldg(&srcs[i + 2]);
            int s3 = __ldg(&srcs[i + 3]);
            unsigned u0 = xw1[(size_t)s0 * 32 + lane];
            unsigned u1 = xw1[(size_t)s1 * 32 + lane];
            unsigned u2 = xw1[(size_t)s2 * 32 + lane];
            unsigned u3 = xw1[(size_t)s3 * 32 + lane];
            ACCL(a, u0, u0); ACCL(b, u1, u1);
            ACCL(a, u2, u2); ACCL(b, u3, u3);
        }
        for (; i < end; i++) {
            int s0 = __ldg(&srcs[i]);
            unsigned u0 = xw1[(size_t)s0 * 32 + lane];
            ACCL(a, u0, u0);
        }
        *(unsigned*)&h[(size_t)node * D + lane * 2] =
            f2bf2(leaky_(a[0] + b[0]), leaky_(a[1] + b[1]));
    }
#undef ACCL
}

// ---------------------------------------------------------------------------
extern "C" void kernel_launch(void* const* d_in, const int* in_sizes, int n_in,
                              void* d_out, int out_size)
{
    const float* features = (const float*)d_in[0];
    const float* id_emb   = (const float*)d_in[1];
    const float* pref     = (const float*)d_in[2];
    const float* mlp_w    = (const float*)d_in[3];
    const float* mlp_b    = (const float*)d_in[4];
    const float* conv1_w  = (const float*)d_in[5];
    const float* lin1_w   = (const float*)d_in[6];
    const float* lin1_b   = (const float*)d_in[7];
    const float* g1_w     = (const float*)d_in[8];
    const float* g1_b     = (const float*)d_in[9];
    const float* conv2_w  = (const float*)d_in[10];
    const float* lin2_w   = (const float*)d_in[11];
    const float* lin2_b   = (const float*)d_in[12];
    const float* g2_w     = (const float*)d_in[13];
    const float* g2_b     = (const float*)d_in[14];
    const int*   ei       = (const int*)d_in[15];
    float* out = (float*)d_out;

    float *pxhat;
    __nv_bfloat16 *px, *pxw, *ph, *px2;
    __nv_bfloat16 *pwmlp, *pwc1, *pwc2, *pwlin1, *pwg1, *pwlin2, *pwg2;
    int *pcnt, *poffs, *ppart, *ppos, *psrcs;
    cudaGetSymbolAddress((void**)&px,     g_x);
    cudaGetSymbolAddress((void**)&pxw,    g_xw);
    cudaGetSymbolAddress((void**)&ph,     g_h);
    cudaGetSymbolAddress((void**)&px2,    g_x2);
    cudaGetSymbolAddress((void**)&pxhat,  g_xhat);
    cudaGetSymbolAddress((void**)&pwmlp,  g_wmlp);
    cudaGetSymbolAddress((void**)&pwc1,   g_wc1);
    cudaGetSymbolAddress((void**)&pwc2,   g_wc2);
    cudaGetSymbolAddress((void**)&pwlin1, g_wlin1);
    cudaGetSymbolAddress((void**)&pwg1,   g_wg1);
    cudaGetSymbolAddress((void**)&pwlin2, g_wlin2);
    cudaGetSymbolAddress((void**)&pwg2,   g_wg2);
    cudaGetSymbolAddress((void**)&pcnt,   g_cnt);
    cudaGetSymbolAddress((void**)&poffs,  g_offs);
    cudaGetSymbolAddress((void**)&ppart,  g_part);
    cudaGetSymbolAddress((void**)&ppos,   g_pos);
    cudaGetSymbolAddress((void**)&psrcs,  g_srcs);

    const int GB_N  = (NN_ + 127) / 128;
    const int NSCAN = NN_ + 1;
    const int NBLK  = (NSCAN + 1023) / 1024;

    static cudaStream_t s_side = nullptr;
    static cudaEvent_t ev_fork = nullptr, ev_join = nullptr, ev_mlp = nullptr,
                       ev_w = nullptr, ev_lin1 = nullptr, ev_g1 = nullptr,
                       ev_lin2 = nullptr;
    if (!s_side) {
        cudaStreamCreateWithFlags(&s_side, cudaStreamNonBlocking);
        cudaEventCreateWithFlags(&ev_fork, cudaEventDisableTiming);
        cudaEventCreateWithFlags(&ev_join, cudaEventDisableTiming);
        cudaEventCreateWithFlags(&ev_mlp,  cudaEventDisableTiming);
        cudaEventCreateWithFlags(&ev_w,    cudaEventDisableTiming);
        cudaEventCreateWithFlags(&ev_lin1, cudaEventDisableTiming);
        cudaEventCreateWithFlags(&ev_g1,   cudaEventDisableTiming);
        cudaEventCreateWithFlags(&ev_lin2, cudaEventDisableTiming);
    }

    // ---- fork: weight prep first (MLP waits only on mlp_w), then CSR ----
    cudaEventRecord(ev_fork, 0);
    cudaStreamWaitEvent(s_side, ev_fork, 0);
    cvt_bf16<<<(DL_ * DF_ / 4 + 255) / 256, 256, 0, s_side>>>(mlp_w, pwmlp, DL_ * DF_);
    cudaEventRecord(ev_w, s_side);
    cudaMemsetAsync(pcnt, 0, NSCAN * sizeof(int), s_side);
    hist_kernel<<<(NE_ + 255) / 256, 256, 0, s_side>>>(ei, pcnt);
    scan1_kernel<<<NBLK, 1024, 0, s_side>>>(pcnt, poffs, ppart, NSCAN);
    scan2_kernel<<<1, 128, 0, s_side>>>(ppart, NBLK);
    scan3_kernel<<<NBLK, 1024, 0, s_side>>>(poffs, ppart, NSCAN);

    // ---- main: MLP (x[NU:] = normalize(features @ mlp_w^T + mlp_b))
    cudaStreamWaitEvent(0, ev_w, 0);
    mma_gemm<128, MODE_NORM, false, true><<<(NI_ + 127) / 128, 256>>>(
        features, pwmlp, px + (size_t)NU_ * DL_, NI_, DF_, mlp_b, nullptr);
    cudaEventRecord(ev_mlp, 0);

    // ---- remaining side-stream work ----
    cudaMemcpyAsync(ppos, poffs, NN_ * sizeof(int), cudaMemcpyDeviceToDevice, s_side);
    reorder_kernel<<<(NE_ + 255) / 256, 256, 0, s_side>>>(ei, ppos, psrcs);
    transpose_cvt<<<(DL_ * DL_ + 255) / 256, 256, 0, s_side>>>(conv1_w, pwc1, DL_, DL_);
    transpose_cvt<<<(DI_ * DI_ + 255) / 256, 256, 0, s_side>>>(conv2_w, pwc2, DI_, DI_);
    cvt_bf16<<<(DI_ * DL_ / 4 + 255) / 256, 256, 0, s_side>>>(lin1_w, pwlin1, DI_ * DL_);
    cvt_bf16<<<(DI_ * DL_ / 4 + 255) / 256, 256, 0, s_side>>>(g1_w, pwg1, DI_ * DL_);
    cvt_bf16<<<(DI_ * DI_ / 4 + 255) / 256, 256, 0, s_side>>>(lin2_w, pwlin2, DI_ * DI_);
    cvt_bf16<<<(DI_ * DI_ / 4 + 255) / 256, 256, 0, s_side>>>(g2_w, pwg2, DI_ * DI_);
    pref_norm_kernel<<<(NU_ * 32 + 255) / 256, 256, 0, s_side>>>(pref, px, NU_);
    cudaEventRecord(ev_join, s_side);

    // side: lin1 overlapped with conv1+scatter (waits MLP)
    cudaStreamWaitEvent(s_side, ev_mlp, 0);
    mma_gemm<64, MODE_LIN, true, false><<<GB_N, 256, 0, s_side>>>(
        px, pwlin1, pxhat, NN_, DL_, lin1_b, id_emb);
    cudaEventRecord(ev_lin1, s_side);

    cudaStreamWaitEvent(0, ev_join, 0);

    // ===== layer 1 (main) =====
    mma_gemm<128, MODE_PLAIN, true, true><<<GB_N, 256>>>(
        px, pwc1, pxw, NN_, DL_, nullptr, nullptr);
    seg_scatter<128><<<(NN_ * 32 + 255) / 256, 256>>>(pxw, poffs, psrcs, ph);
    cudaStreamWaitEvent(0, ev_lin1, 0);
    mma_gemm<64, MODE_G, true, true><<<GB_N, 256>>>(
        ph, pwg1, px2, NN_, DL_, g1_b, pxhat);
    cudaEventRecord(ev_g1, 0);

    // side: lin2 overlapped with conv2+scatter64
    cudaStreamWaitEvent(s_side, ev_g1, 0);
    mma_gemm<64, MODE_LIN, true, false><<<GB_N, 256, 0, s_side>>>(
        px2, pwlin2, pxhat, NN_, DI_, lin2_b, id_emb);
    cudaEventRecord(ev_lin2, s_side);

    // ===== layer 2 (main) =====
    mma_gemm<64, MODE_PLAIN, true, true><<<GB_N, 256>>>(
        px2, pwc2, pxw, NN_, DI_, nullptr, nullptr);
    seg_scatter<64><<<(NN_ * 32 + 255) / 256, 256>>>(pxw, poffs, psrcs, ph);
    cudaStreamWaitEvent(0, ev_lin2, 0);
    mma_gemm<64, MODE_G, true, false><<<GB_N, 256>>>(
        ph, pwg2, out, NN_, DI_, g2_b, pxhat);
}